// round 1
// baseline (speedup 1.0000x reference)
#include <cuda_runtime.h>

#define NT 256
#define SST 132           // padded stride (floats) for transposed activation arrays
#define BTOT 16384

// smem floats:
// sAct[128][SST] (rows 0..63 user, 64..127 item), sHT[64][SST] (head),
// sW1[128*128], sW2[128*64], sWul[64*64], sWv[4*64], bul[64], b1[128], b2[64], w3[64]
#define SMEM_FLOATS (128*SST + 64*SST + 128*128 + 128*64 + 64*64 + 256 + 64 + 128 + 64 + 64)
#define SMEM_BYTES (SMEM_FLOATS * 4)

__global__ __launch_bounds__(NT, 1)
void multikr_kernel(const int* __restrict__ user_id,
                    const int* __restrict__ item_id,
                    const float* __restrict__ rec_target,
                    const float* __restrict__ user_emb,
                    const float* __restrict__ item_emb,
                    const float* __restrict__ entity_emb,
                    const float* __restrict__ w_vv,
                    const float* __restrict__ w_ev,
                    const float* __restrict__ w_ve,
                    const float* __restrict__ w_ee,
                    const float* __restrict__ b_v,
                    const float* __restrict__ b_e,
                    const float* __restrict__ Wul,
                    const float* __restrict__ bul,
                    const float* __restrict__ W1,
                    const float* __restrict__ b1,
                    const float* __restrict__ W2,
                    const float* __restrict__ b2,
                    const float* __restrict__ W3,
                    const float* __restrict__ b3,
                    float* __restrict__ out,
                    int out_size)
{
    extern __shared__ float sm[];
    float* sAct = sm;                   // [128][SST]
    float* sHT  = sAct + 128 * SST;     // [64][SST]
    float* sW1  = sHT  + 64 * SST;      // [128*128]
    float* sW2  = sW1  + 128 * 128;     // [128*64]
    float* sWul = sW2  + 128 * 64;      // [64*64]
    float* sWv  = sWul + 64 * 64;       // [256]: w_vv | w_ev | w_ve | w_ee
    float* sBul = sWv  + 256;           // [64]
    float* sB1  = sBul + 64;            // [128]
    float* sB2  = sB1  + 128;           // [64]
    float* sW3  = sB2  + 64;            // [64]

    const int t = threadIdx.x;
    const int base = blockIdx.x * 128;

    // ---- cooperative weight load (all L2-resident, ~113KB) ----
    {
        const float4* s4 = (const float4*)W1; float4* d4 = (float4*)sW1;
        #pragma unroll 4
        for (int i = t; i < 128 * 128 / 4; i += NT) d4[i] = s4[i];
        s4 = (const float4*)W2; d4 = (float4*)sW2;
        #pragma unroll 2
        for (int i = t; i < 128 * 64 / 4; i += NT) d4[i] = s4[i];
        s4 = (const float4*)Wul; d4 = (float4*)sWul;
        for (int i = t; i < 64 * 64 / 4; i += NT) d4[i] = s4[i];
        if (t < 64) {
            sWv[t]       = w_vv[t];
            sWv[64 + t]  = w_ev[t];
            sWv[128 + t] = w_ve[t];
            sWv[192 + t] = w_ee[t];
            sBul[t] = bul[t];
            sB2[t]  = b2[t];
            sW3[t]  = W3[t];
        }
        if (t < 128) sB1[t] = b1[t];
    }

    // ---- gather embeddings (write transposed [d][s]) ----
    if (t < 128) {
        const int s = t;
        const int uid = user_id[base + s];
        const float4* r = (const float4*)(user_emb + (size_t)uid * 64);
        #pragma unroll
        for (int d4i = 0; d4i < 16; d4i++) {
            float4 v = r[d4i]; int d = d4i * 4;
            sAct[(d + 0) * SST + s] = v.x;
            sAct[(d + 1) * SST + s] = v.y;
            sAct[(d + 2) * SST + s] = v.z;
            sAct[(d + 3) * SST + s] = v.w;
        }
    } else {
        const int s = t - 128;
        const int iid = item_id[base + s];
        const float4* r = (const float4*)(item_emb + (size_t)iid * 64);
        #pragma unroll
        for (int d4i = 0; d4i < 16; d4i++) {
            float4 v = r[d4i]; int d = d4i * 4;
            sAct[(64 + d + 0) * SST + s] = v.x;
            sAct[(64 + d + 1) * SST + s] = v.y;
            sAct[(64 + d + 2) * SST + s] = v.z;
            sAct[(64 + d + 3) * SST + s] = v.w;
        }
    }
    {   // head: 2 threads per sample
        const int s = t >> 1, half = t & 1;
        const int iid = item_id[base + s];
        const float4* r = (const float4*)(entity_emb + (size_t)iid * 64);
        #pragma unroll
        for (int d4i = half * 8; d4i < half * 8 + 8; d4i++) {
            float4 v = r[d4i]; int d = d4i * 4;
            sHT[(d + 0) * SST + s] = v.x;
            sHT[(d + 1) * SST + s] = v.y;
            sHT[(d + 2) * SST + s] = v.z;
            sHT[(d + 3) * SST + s] = v.w;
        }
    }
    __syncthreads();

    const int tx = t & 15, ty = t >> 4;
    const float bv = b_v[0], be = b_e[0];

    // ---- 2x (user 64x64 MLP + cross&compress) ----
    #pragma unroll 1
    for (int layer = 0; layer < 2; layer++) {
        // user: out[s][j] = relu(bul[j] + sum_k u[s][k]*Wul[k][j]); 8 samples x 4 cols per thread
        float acc[8][4];
        #pragma unroll
        for (int si = 0; si < 8; si++)
            #pragma unroll
            for (int ji = 0; ji < 4; ji++) acc[si][ji] = sBul[tx * 4 + ji];
        #pragma unroll 8
        for (int k = 0; k < 64; k++) {
            float4 b = *(const float4*)&sWul[k * 64 + tx * 4];
            const float* ap = &sAct[k * SST + ty * 8];
            float4 a0 = *(const float4*)ap;
            float4 a1 = *(const float4*)(ap + 4);
            float a[8] = {a0.x, a0.y, a0.z, a0.w, a1.x, a1.y, a1.z, a1.w};
            #pragma unroll
            for (int si = 0; si < 8; si++) {
                acc[si][0] = fmaf(a[si], b.x, acc[si][0]);
                acc[si][1] = fmaf(a[si], b.y, acc[si][1]);
                acc[si][2] = fmaf(a[si], b.z, acc[si][2]);
                acc[si][3] = fmaf(a[si], b.w, acc[si][3]);
            }
        }
        __syncthreads();
        #pragma unroll
        for (int ji = 0; ji < 4; ji++)
            #pragma unroll
            for (int si = 0; si < 8; si++)
                sAct[(tx * 4 + ji) * SST + ty * 8 + si] = fmaxf(acc[si][ji], 0.0f);
        __syncthreads();

        // cross&compress: 1 thread per sample, column-local (no hazards)
        if (t < 128) {
            const int s = t;
            float s1 = 0.f, s2 = 0.f, s3 = 0.f, s4 = 0.f;
            #pragma unroll 8
            for (int k = 0; k < 64; k++) {
                float it = sAct[(64 + k) * SST + s];
                float hd = sHT[k * SST + s];
                s1 = fmaf(hd, sWv[k], s1);
                s2 = fmaf(it, sWv[64 + k], s2);
                s3 = fmaf(hd, sWv[128 + k], s3);
                s4 = fmaf(it, sWv[192 + k], s4);
            }
            #pragma unroll 8
            for (int k = 0; k < 64; k++) {
                float it = sAct[(64 + k) * SST + s];
                float hd = sHT[k * SST + s];
                sAct[(64 + k) * SST + s] = fmaf(it, s1, fmaf(hd, s2, bv));
                sHT[k * SST + s]         = fmaf(it, s3, fmaf(hd, s4, be));
            }
        }
        __syncthreads();
    }

    // ---- tower GEMM1: h1[s][j] = relu(b1[j] + sum_{k<128} high[s][k]*W1[k][j]); 8x8 tile ----
    {
        float acc[8][8];
        #pragma unroll
        for (int si = 0; si < 8; si++)
            #pragma unroll
            for (int ji = 0; ji < 8; ji++) acc[si][ji] = sB1[tx * 8 + ji];
        #pragma unroll 4
        for (int k = 0; k < 128; k++) {
            const float* bp = &sW1[k * 128 + tx * 8];
            float4 b0 = *(const float4*)bp;
            float4 b1v = *(const float4*)(bp + 4);
            const float* ap = &sAct[k * SST + ty * 8];
            float4 a0 = *(const float4*)ap;
            float4 a1 = *(const float4*)(ap + 4);
            float a[8] = {a0.x, a0.y, a0.z, a0.w, a1.x, a1.y, a1.z, a1.w};
            float b[8] = {b0.x, b0.y, b0.z, b0.w, b1v.x, b1v.y, b1v.z, b1v.w};
            #pragma unroll
            for (int si = 0; si < 8; si++)
                #pragma unroll
                for (int ji = 0; ji < 8; ji++)
                    acc[si][ji] = fmaf(a[si], b[ji], acc[si][ji]);
        }
        __syncthreads();
        #pragma unroll
        for (int ji = 0; ji < 8; ji++)
            #pragma unroll
            for (int si = 0; si < 8; si++)
                sAct[(tx * 8 + ji) * SST + ty * 8 + si] = fmaxf(acc[si][ji], 0.0f);
        __syncthreads();
    }

    // ---- tower GEMM2 (128->64) fused with final 64->1 + relu ----
    {
        float acc[8][4];
        #pragma unroll
        for (int si = 0; si < 8; si++)
            #pragma unroll
            for (int ji = 0; ji < 4; ji++) acc[si][ji] = sB2[tx * 4 + ji];
        #pragma unroll 4
        for (int k = 0; k < 128; k++) {
            float4 b = *(const float4*)&sW2[k * 64 + tx * 4];
            const float* ap = &sAct[k * SST + ty * 8];
            float4 a0 = *(const float4*)ap;
            float4 a1 = *(const float4*)(ap + 4);
            float a[8] = {a0.x, a0.y, a0.z, a0.w, a1.x, a1.y, a1.z, a1.w};
            #pragma unroll
            for (int si = 0; si < 8; si++) {
                acc[si][0] = fmaf(a[si], b.x, acc[si][0]);
                acc[si][1] = fmaf(a[si], b.y, acc[si][1]);
                acc[si][2] = fmaf(a[si], b.z, acc[si][2]);
                acc[si][3] = fmaf(a[si], b.w, acc[si][3]);
            }
        }
        float w3v0 = sW3[tx * 4 + 0], w3v1 = sW3[tx * 4 + 1];
        float w3v2 = sW3[tx * 4 + 2], w3v3 = sW3[tx * 4 + 3];
        float p[8];
        #pragma unroll
        for (int si = 0; si < 8; si++) {
            float h0 = fmaxf(acc[si][0], 0.0f);
            float h1h = fmaxf(acc[si][1], 0.0f);
            float h2 = fmaxf(acc[si][2], 0.0f);
            float h3 = fmaxf(acc[si][3], 0.0f);
            p[si] = fmaf(h0, w3v0, fmaf(h1h, w3v1, fmaf(h2, w3v2, h3 * w3v3)));
        }
        // reduce across the 16 tx lanes (width-16 butterfly)
        #pragma unroll
        for (int off = 8; off > 0; off >>= 1)
            #pragma unroll
            for (int si = 0; si < 8; si++)
                p[si] += __shfl_xor_sync(0xffffffffu, p[si], off, 16);
        const float b3v = b3[0];
        if (tx == 0) {
            #pragma unroll
            for (int si = 0; si < 8; si++)
                out[base + ty * 8 + si] = fmaxf(p[si] + b3v, 0.0f);
        }
    }

    // ---- rec_target passthrough (second output of the tuple) ----
    if (out_size >= 2 * BTOT && t < 128)
        out[BTOT + base + t] = rec_target[base + t];
}

extern "C" void kernel_launch(void* const* d_in, const int* in_sizes, int n_in,
                              void* d_out, int out_size)
{
    const int*   user_id    = (const int*)d_in[0];
    const int*   item_id    = (const int*)d_in[1];
    const float* rec_target = (const float*)d_in[2];
    const float* user_emb   = (const float*)d_in[3];
    const float* item_emb   = (const float*)d_in[4];
    const float* entity_emb = (const float*)d_in[5];
    const float* w_vv = (const float*)d_in[6];
    const float* w_ev = (const float*)d_in[7];
    const float* w_ve = (const float*)d_in[8];
    const float* w_ee = (const float*)d_in[9];
    const float* b_v  = (const float*)d_in[10];
    const float* b_e  = (const float*)d_in[11];
    const float* Wul  = (const float*)d_in[12];
    const float* bul  = (const float*)d_in[13];
    const float* W1   = (const float*)d_in[14];
    const float* b1   = (const float*)d_in[15];
    const float* W2   = (const float*)d_in[16];
    const float* b2   = (const float*)d_in[17];
    const float* W3   = (const float*)d_in[18];
    const float* b3   = (const float*)d_in[19];

    cudaFuncSetAttribute(multikr_kernel,
                         cudaFuncAttributeMaxDynamicSharedMemorySize, SMEM_BYTES);

    const int n = in_sizes[0];      // 16384
    const int nblk = n / 128;       // 128 blocks = one wave
    multikr_kernel<<<nblk, NT, SMEM_BYTES>>>(
        user_id, item_id, rec_target, user_emb, item_emb, entity_emb,
        w_vv, w_ev, w_ve, w_ee, b_v, b_e, Wul, bul,
        W1, b1, W2, b2, W3, b3,
        (float*)d_out, out_size);
}

// round 3
// speedup vs baseline: 1.5251x; 1.5251x over previous
#include <cuda_runtime.h>
#include <cstdint>

#define NT 256
#define SST 132            // sAct row stride in floats (528B = 16 mod 128 -> ldmatrix conflict-free)
#define BTOT 16384

// ---- dynamic smem layout (float offsets) ----
#define F_ACT   0                       // sAct[128][SST]                = 16896
#define F_W1    (F_ACT + 128*SST)       // blocked 16x16 tiles           = 16384
#define F_WUL   (F_W1 + 16384)          // blocked 8x8 tiles             = 4096
#define F_ITEM  (F_WUL + 4096)          // sItem[k=64][s=128]            = 8192
#define F_HEAD  (F_ITEM + 8192)         // sHead[64][128] (ALIAS sW2)    = 8192
#define F_WV    (F_HEAD + 8192)         // 256: w_vv|w_ev|w_ve|w_ee
#define F_BUL   (F_WV + 256)            // 64
#define F_B1    (F_BUL + 64)            // 128
#define F_B2    (F_B1 + 128)            // 64
#define F_W3    (F_B2 + 64)             // 64
#define SMEM_FLOATS (F_W3 + 64)
#define SMEM_BYTES  (SMEM_FLOATS * 4 + 256)

__device__ __forceinline__ uint32_t smem_u32(const void* p) {
    uint32_t a;
    asm("{ .reg .u64 t; cvta.to.shared.u64 t, %1; cvt.u32.u64 %0, t; }" : "=r"(a) : "l"(p));
    return a;
}
__device__ __forceinline__ float tf32r(float x) {
    uint32_t u;
    asm("cvt.rna.tf32.f32 %0, %1;" : "=r"(u) : "f"(x));
    return __uint_as_float(u);
}
__device__ __forceinline__ void ldsm4(uint32_t* r, uint32_t addr) {
    asm volatile("ldmatrix.sync.aligned.m8n8.x4.shared.b16 {%0,%1,%2,%3}, [%4];"
                 : "=r"(r[0]), "=r"(r[1]), "=r"(r[2]), "=r"(r[3]) : "r"(addr));
}
__device__ __forceinline__ void mma8(float* c, const uint32_t* a, const uint32_t* b) {
    asm("mma.sync.aligned.m16n8k8.row.col.f32.tf32.tf32.f32 "
        "{%0,%1,%2,%3},{%4,%5,%6,%7},{%8,%9},{%0,%1,%2,%3};"
        : "+f"(c[0]), "+f"(c[1]), "+f"(c[2]), "+f"(c[3])
        : "r"(a[0]), "r"(a[1]), "r"(a[2]), "r"(a[3]), "r"(b[0]), "r"(b[1]));
}
// blocked B layout: float index of element (n,k); K8 = K/8
__device__ __forceinline__ int bwoff(int n, int k, int K8) {
    return (((n >> 3) * K8 + (k >> 3)) << 6) + (((k >> 2) & 1) << 5) + ((n & 7) << 2) + (k & 3);
}

__global__ __launch_bounds__(NT, 1)
void multikr_mma_kernel(const int* __restrict__ user_id,
                        const int* __restrict__ item_id,
                        const float* __restrict__ rec_target,
                        const float* __restrict__ user_emb,
                        const float* __restrict__ item_emb,
                        const float* __restrict__ entity_emb,
                        const float* __restrict__ w_vv,
                        const float* __restrict__ w_ev,
                        const float* __restrict__ w_ve,
                        const float* __restrict__ w_ee,
                        const float* __restrict__ b_v,
                        const float* __restrict__ b_e,
                        const float* __restrict__ Wul,
                        const float* __restrict__ bul,
                        const float* __restrict__ W1,
                        const float* __restrict__ b1,
                        const float* __restrict__ W2,
                        const float* __restrict__ b2,
                        const float* __restrict__ W3,
                        const float* __restrict__ b3,
                        float* __restrict__ out,
                        int out_size)
{
    extern __shared__ float sm[];
    float* sAct  = sm + F_ACT;
    float* sW1   = sm + F_W1;
    float* sWul  = sm + F_WUL;
    float* sItem = sm + F_ITEM;
    float* sHead = sm + F_HEAD;    // aliased: becomes sW2 after layers
    float* sW2   = sm + F_HEAD;
    float* sWV   = sm + F_WV;
    float* sBUL  = sm + F_BUL;
    float* sB1   = sm + F_B1;
    float* sB2   = sm + F_B2;
    float* sW3   = sm + F_W3;

    const int t   = threadIdx.x;
    const int l   = t & 31;
    const int wid = t >> 5;
    const int wm  = wid & 1;        // M half: rows wm*64 .. +63
    const int wn  = wid >> 1;       // N quarter
    const int mtx = l >> 3, p = l & 7;
    const int base = blockIdx.x * 128;

    const uint32_t uAct = smem_u32(sAct);
    const uint32_t uW1  = smem_u32(sW1);
    const uint32_t uWul = smem_u32(sWul);
    const uint32_t uW2  = smem_u32(sW2);

    // per-thread ldmatrix offsets (bytes)
    const uint32_t aoffT  = 4u * (((mtx & 1) * 8 + p) * SST + (mtx >> 1) * 4);
    const uint32_t boffT8  = 4u * (((mtx >> 1) * 8  << 6) + ((mtx & 1) << 5) + (p << 2));
    const uint32_t boffT16 = 4u * (((mtx >> 1) * 16 << 6) + ((mtx & 1) << 5) + (p << 2));

    // ================== gathers ==================
    {
        const int s = t & 127, half = t >> 7;
        if (half == 0) {
            const int uid = user_id[base + s];
            const float4* up = (const float4*)(user_emb + (size_t)uid * 64);
            #pragma unroll
            for (int j = 0; j < 16; j++) {
                float4 v = up[j];
                float4 w = make_float4(tf32r(v.x), tf32r(v.y), tf32r(v.z), tf32r(v.w));
                *(float4*)&sAct[s * SST + j * 4] = w;
            }
        } else {
            const int iid = item_id[base + s];
            const float4* ip = (const float4*)(item_emb + (size_t)iid * 64);
            const float4* hp = (const float4*)(entity_emb + (size_t)iid * 64);
            #pragma unroll
            for (int j = 0; j < 16; j++) {
                float4 v = ip[j];
                sItem[(j * 4 + 0) * 128 + s] = v.x;
                sItem[(j * 4 + 1) * 128 + s] = v.y;
                sItem[(j * 4 + 2) * 128 + s] = v.z;
                sItem[(j * 4 + 3) * 128 + s] = v.w;
            }
            #pragma unroll
            for (int j = 0; j < 16; j++) {
                float4 v = hp[j];
                sHead[(j * 4 + 0) * 128 + s] = v.x;
                sHead[(j * 4 + 1) * 128 + s] = v.y;
                sHead[(j * 4 + 2) * 128 + s] = v.z;
                sHead[(j * 4 + 3) * 128 + s] = v.w;
            }
        }
    }
    // ================== weight staging (blocked, tf32) ==================
    {   // Wul: [k=64][n=64] -> sWul[n][k] blocked K8=8
        const int n = t & 63, k0 = (t >> 6) * 16;
        #pragma unroll
        for (int kk = 0; kk < 16; kk++)
            sWul[bwoff(n, k0 + kk, 8)] = tf32r(Wul[(k0 + kk) * 64 + n]);
    }
    {   // W1: [k=128][n=128] -> sW1[n][k] blocked K8=16
        const int n = t & 127, k0 = (t >> 7) * 64;
        #pragma unroll 8
        for (int kk = 0; kk < 64; kk++)
            sW1[bwoff(n, k0 + kk, 16)] = tf32r(W1[(k0 + kk) * 128 + n]);
    }
    if (t < 64) {
        sWV[t]       = w_vv[t];
        sWV[64 + t]  = w_ev[t];
        sWV[128 + t] = w_ve[t];
        sWV[192 + t] = w_ee[t];
        sBUL[t] = bul[t];
        sB2[t]  = b2[t];
        sW3[t]  = W3[t];
    }
    if (t < 128) sB1[t] = b1[t];
    __syncthreads();

    const float bvv = b_v[0], bee = b_e[0];

    // ================== 2x (user MLP mma + cross&compress) ==================
    #pragma unroll 1
    for (int layer = 0; layer < 2; layer++) {
        // user MLP: M=128, N=64, K=64.  warp: 4 m-tiles, 2 n-tiles
        float acc[4][2][4];
        #pragma unroll
        for (int mt = 0; mt < 4; mt++)
            #pragma unroll
            for (int nt = 0; nt < 2; nt++)
                #pragma unroll
                for (int i = 0; i < 4; i++) acc[mt][nt][i] = 0.f;
        {
            const int nb0 = wn * 2;
            #pragma unroll
            for (int k8 = 0; k8 < 8; k8++) {
                uint32_t a[4][4], b[4];
                #pragma unroll
                for (int mt = 0; mt < 4; mt++)
                    ldsm4(a[mt], uAct + 4u * ((wm * 64 + mt * 16) * SST + k8 * 8) + aoffT);
                ldsm4(b, uWul + 4u * ((nb0 * 8 + k8) << 6) + boffT8);
                #pragma unroll
                for (int mt = 0; mt < 4; mt++) {
                    mma8(acc[mt][0], a[mt], b);
                    mma8(acc[mt][1], a[mt], b + 2);
                }
            }
        }
        __syncthreads();   // all reads of sAct cols 0-63 done
        // epilogue: relu(+bul), tf32 round, write back to sAct cols 0-63
        {
            const int r0b = wm * 64 + (l >> 2);
            const int cb  = wn * 16 + 2 * (l & 3);
            #pragma unroll
            for (int mt = 0; mt < 4; mt++)
                #pragma unroll
                for (int nt = 0; nt < 2; nt++) {
                    int c = cb + nt * 8;
                    float bb0 = sBUL[c], bb1 = sBUL[c + 1];
                    int r0 = r0b + mt * 16;
                    float2 v0, v1;
                    v0.x = tf32r(fmaxf(acc[mt][nt][0] + bb0, 0.f));
                    v0.y = tf32r(fmaxf(acc[mt][nt][1] + bb1, 0.f));
                    v1.x = tf32r(fmaxf(acc[mt][nt][2] + bb0, 0.f));
                    v1.y = tf32r(fmaxf(acc[mt][nt][3] + bb1, 0.f));
                    *(float2*)&sAct[r0 * SST + c] = v0;
                    *(float2*)&sAct[(r0 + 8) * SST + c] = v1;
                }
        }
        // cross&compress in fp32 on sItem/sHead (independent of sAct)
        {
            const int cs = t >> 1, kh = t & 1;
            float s1 = 0.f, s2 = 0.f, s3 = 0.f, s4 = 0.f;
            #pragma unroll 8
            for (int kk = 0; kk < 32; kk++) {
                int k = kh * 32 + kk;
                float it = sItem[k * 128 + cs];
                float hd = sHead[k * 128 + cs];
                s1 = fmaf(hd, sWV[k], s1);
                s2 = fmaf(it, sWV[64 + k], s2);
                s3 = fmaf(hd, sWV[128 + k], s3);
                s4 = fmaf(it, sWV[192 + k], s4);
            }
            s1 += __shfl_xor_sync(0xffffffffu, s1, 1);
            s2 += __shfl_xor_sync(0xffffffffu, s2, 1);
            s3 += __shfl_xor_sync(0xffffffffu, s3, 1);
            s4 += __shfl_xor_sync(0xffffffffu, s4, 1);
            #pragma unroll 8
            for (int kk = 0; kk < 32; kk++) {
                int k = kh * 32 + kk;
                float it = sItem[k * 128 + cs];
                float hd = sHead[k * 128 + cs];
                sItem[k * 128 + cs] = fmaf(it, s1, fmaf(hd, s2, bvv));
                sHead[k * 128 + cs] = fmaf(it, s3, fmaf(hd, s4, bee));
            }
        }
        __syncthreads();
    }

    // ================== item -> sAct cols 64..127 (tf32); stage sW2 over dead sHead ==================
    {
        const int s = t & 127, kh = t >> 7;
        #pragma unroll
        for (int j = 0; j < 8; j++) {
            int k = kh * 32 + j * 4;
            float4 v;
            v.x = tf32r(sItem[(k + 0) * 128 + s]);
            v.y = tf32r(sItem[(k + 1) * 128 + s]);
            v.z = tf32r(sItem[(k + 2) * 128 + s]);
            v.w = tf32r(sItem[(k + 3) * 128 + s]);
            *(float4*)&sAct[s * SST + 64 + k] = v;
        }
    }
    __syncthreads();   // sHead fully dead now
    {   // W2: [k=128][n=64] -> sW2[n][k] blocked K8=16 (aliases sHead)
        const int n = t & 63, k0 = (t >> 6) * 32;
        #pragma unroll 8
        for (int kk = 0; kk < 32; kk++)
            sW2[bwoff(n, k0 + kk, 16)] = tf32r(W2[(k0 + kk) * 64 + n]);
    }
    __syncthreads();

    // ================== GEMM1: M=128, N=128, K=128.  warp: 4 m-tiles, 4 n-tiles ==================
    {
        float acc[4][4][4];
        #pragma unroll
        for (int mt = 0; mt < 4; mt++)
            #pragma unroll
            for (int nt = 0; nt < 4; nt++)
                #pragma unroll
                for (int i = 0; i < 4; i++) acc[mt][nt][i] = 0.f;
        const int nb0 = wn * 4;
        #pragma unroll
        for (int k8 = 0; k8 < 16; k8++) {
            uint32_t a[4][4], b[8];
            #pragma unroll
            for (int mt = 0; mt < 4; mt++)
                ldsm4(a[mt], uAct + 4u * ((wm * 64 + mt * 16) * SST + k8 * 8) + aoffT);
            ldsm4(b,     uW1 + 4u * (((nb0 + 0) * 16 + k8) << 6) + boffT16);
            ldsm4(b + 4, uW1 + 4u * (((nb0 + 2) * 16 + k8) << 6) + boffT16);
            #pragma unroll
            for (int mt = 0; mt < 4; mt++) {
                mma8(acc[mt][0], a[mt], b);
                mma8(acc[mt][1], a[mt], b + 2);
                mma8(acc[mt][2], a[mt], b + 4);
                mma8(acc[mt][3], a[mt], b + 6);
            }
        }
        __syncthreads();
        // epilogue: h1 = relu(+b1), tf32, into sAct cols 0-127
        const int r0b = wm * 64 + (l >> 2);
        const int cb  = wn * 32 + 2 * (l & 3);
        #pragma unroll
        for (int mt = 0; mt < 4; mt++)
            #pragma unroll
            for (int nt = 0; nt < 4; nt++) {
                int c = cb + nt * 8;
                float bb0 = sB1[c], bb1 = sB1[c + 1];
                int r0 = r0b + mt * 16;
                float2 v0, v1;
                v0.x = tf32r(fmaxf(acc[mt][nt][0] + bb0, 0.f));
                v0.y = tf32r(fmaxf(acc[mt][nt][1] + bb1, 0.f));
                v1.x = tf32r(fmaxf(acc[mt][nt][2] + bb0, 0.f));
                v1.y = tf32r(fmaxf(acc[mt][nt][3] + bb1, 0.f));
                *(float2*)&sAct[r0 * SST + c] = v0;
                *(float2*)&sAct[(r0 + 8) * SST + c] = v1;
            }
    }
    __syncthreads();

    // ================== GEMM2: M=128, N=64, K=128.  warp: 4 m-tiles, 2 n-tiles ==================
    {
        float acc[4][2][4];
        #pragma unroll
        for (int mt = 0; mt < 4; mt++)
            #pragma unroll
            for (int nt = 0; nt < 2; nt++)
                #pragma unroll
                for (int i = 0; i < 4; i++) acc[mt][nt][i] = 0.f;
        const int nb0 = wn * 2;
        #pragma unroll
        for (int k8 = 0; k8 < 16; k8++) {
            uint32_t a[4][4], b[4];
            #pragma unroll
            for (int mt = 0; mt < 4; mt++)
                ldsm4(a[mt], uAct + 4u * ((wm * 64 + mt * 16) * SST + k8 * 8) + aoffT);
            ldsm4(b, uW2 + 4u * ((nb0 * 16 + k8) << 6) + boffT16);
            #pragma unroll
            for (int mt = 0; mt < 4; mt++) {
                mma8(acc[mt][0], a[mt], b);
                mma8(acc[mt][1], a[mt], b + 2);
            }
        }
        __syncthreads();
        // epilogue: h2 = relu(+b2) (fp32, no rounding) into sAct cols 0-63
        const int r0b = wm * 64 + (l >> 2);
        const int cb  = wn * 16 + 2 * (l & 3);
        #pragma unroll
        for (int mt = 0; mt < 4; mt++)
            #pragma unroll
            for (int nt = 0; nt < 2; nt++) {
                int c = cb + nt * 8;
                float bb0 = sB2[c], bb1 = sB2[c + 1];
                int r0 = r0b + mt * 16;
                float2 v0, v1;
                v0.x = fmaxf(acc[mt][nt][0] + bb0, 0.f);
                v0.y = fmaxf(acc[mt][nt][1] + bb1, 0.f);
                v1.x = fmaxf(acc[mt][nt][2] + bb0, 0.f);
                v1.y = fmaxf(acc[mt][nt][3] + bb1, 0.f);
                *(float2*)&sAct[r0 * SST + c] = v0;
                *(float2*)&sAct[(r0 + 8) * SST + c] = v1;
            }
    }
    __syncthreads();

    // ================== final 64->1 + relu; rec_target passthrough ==================
    if (t < 128) {
        const int s = t;
        float psum = 0.f;
        #pragma unroll
        for (int j = 0; j < 16; j++) {
            float4 v = *(const float4*)&sAct[s * SST + j * 4];
            float4 w = *(const float4*)&sW3[j * 4];
            psum = fmaf(v.x, w.x, fmaf(v.y, w.y, fmaf(v.z, w.z, fmaf(v.w, w.w, psum))));
        }
        out[base + s] = fmaxf(psum + b3[0], 0.f);
        if (out_size >= 2 * BTOT)
            out[BTOT + base + s] = rec_target[base + s];
    }
}

extern "C" void kernel_launch(void* const* d_in, const int* in_sizes, int n_in,
                              void* d_out, int out_size)
{
    const int*   user_id    = (const int*)d_in[0];
    const int*   item_id    = (const int*)d_in[1];
    const float* rec_target = (const float*)d_in[2];
    const float* user_emb   = (const float*)d_in[3];
    const float* item_emb   = (const float*)d_in[4];
    const float* entity_emb = (const float*)d_in[5];
    const float* w_vv = (const float*)d_in[6];
    const float* w_ev = (const float*)d_in[7];
    const float* w_ve = (const float*)d_in[8];
    const float* w_ee = (const float*)d_in[9];
    const float* b_v  = (const float*)d_in[10];
    const float* b_e  = (const float*)d_in[11];
    const float* Wul  = (const float*)d_in[12];
    const float* bul  = (const float*)d_in[13];
    const float* W1   = (const float*)d_in[14];
    const float* b1   = (const float*)d_in[15];
    const float* W2   = (const float*)d_in[16];
    const float* b2   = (const float*)d_in[17];
    const float* W3   = (const float*)d_in[18];
    const float* b3   = (const float*)d_in[19];

    cudaFuncSetAttribute(multikr_mma_kernel,
                         cudaFuncAttributeMaxDynamicSharedMemorySize, SMEM_BYTES);

    const int n = in_sizes[0];      // 16384
    const int nblk = n / 128;       // 128 blocks, one wave
    multikr_mma_kernel<<<nblk, NT, SMEM_BYTES>>>(
        user_id, item_id, rec_target, user_emb, item_emb, entity_emb,
        w_vv, w_ev, w_ve, w_ee, b_v, b_e, Wul, bul,
        W1, b1, W2, b2, W3, b3,
        (float*)d_out, out_size);
}

// round 4
// speedup vs baseline: 1.7912x; 1.1745x over previous
#include <cuda_runtime.h>
#include <cstdint>

#define NT 256
#define SST 132            // sAct row stride (floats): bank base 4s, f4 conflict-free
#define HST 68             // sHead row stride
#define BTOT 16384

// ---- dynamic smem layout (float offsets) ----
#define F_ACT   0                        // sAct[128][SST]  = 16896
#define F_W1    (F_ACT + 128*SST)        // 16384 (blocked K8=16)
#define F_WUL   (F_W1 + 16384)           // 4096  (blocked K8=8)
#define F_W2    (F_WUL + 4096)           // 8192  (blocked K8=16)
#define F_HEAD  (F_W2 + 8192)            // sHead[128][HST] = 8704
#define F_WV    (F_HEAD + 128*HST)       // 256: w_vv|w_ev|w_ve|w_ee
#define F_BUL   (F_WV + 256)             // 64
#define F_B1    (F_BUL + 64)             // 128
#define F_B2    (F_B1 + 128)             // 64
#define F_W3    (F_B2 + 64)              // 64
#define SMEM_FLOATS (F_W3 + 64)
#define SMEM_BYTES  (SMEM_FLOATS * 4 + 128)

__device__ __forceinline__ uint32_t smem_u32(const void* p) {
    uint32_t a;
    asm("{ .reg .u64 t; cvta.to.shared.u64 t, %1; cvt.u32.u64 %0, t; }" : "=r"(a) : "l"(p));
    return a;
}
__device__ __forceinline__ float tf32r(float x) {
    uint32_t u;
    asm("cvt.rna.tf32.f32 %0, %1;" : "=r"(u) : "f"(x));
    return __uint_as_float(u);
}
__device__ __forceinline__ void ldsm4(uint32_t* r, uint32_t addr) {
    asm volatile("ldmatrix.sync.aligned.m8n8.x4.shared.b16 {%0,%1,%2,%3}, [%4];"
                 : "=r"(r[0]), "=r"(r[1]), "=r"(r[2]), "=r"(r[3]) : "r"(addr));
}
__device__ __forceinline__ void mma8(float* c, const uint32_t* a, const uint32_t* b) {
    asm("mma.sync.aligned.m16n8k8.row.col.f32.tf32.tf32.f32 "
        "{%0,%1,%2,%3},{%4,%5,%6,%7},{%8,%9},{%0,%1,%2,%3};"
        : "+f"(c[0]), "+f"(c[1]), "+f"(c[2]), "+f"(c[3])
        : "r"(a[0]), "r"(a[1]), "r"(a[2]), "r"(a[3]), "r"(b[0]), "r"(b[1]));
}
// blocked B layout: float index of element (n,k); K8 = K/8
__device__ __forceinline__ int bwoff(int n, int k, int K8) {
    return (((n >> 3) * K8 + (k >> 3)) << 6) + (((k >> 2) & 1) << 5) + ((n & 7) << 2) + (k & 3);
}
#define GBAR() asm volatile("bar.sync %0, 128;" :: "r"(g + 1) : "memory")

__global__ __launch_bounds__(NT, 1)
void multikr_mma_kernel(const int* __restrict__ user_id,
                        const int* __restrict__ item_id,
                        const float* __restrict__ rec_target,
                        const float* __restrict__ user_emb,
                        const float* __restrict__ item_emb,
                        const float* __restrict__ entity_emb,
                        const float* __restrict__ w_vv,
                        const float* __restrict__ w_ev,
                        const float* __restrict__ w_ve,
                        const float* __restrict__ w_ee,
                        const float* __restrict__ b_v,
                        const float* __restrict__ b_e,
                        const float* __restrict__ Wul,
                        const float* __restrict__ bul,
                        const float* __restrict__ W1,
                        const float* __restrict__ b1,
                        const float* __restrict__ W2,
                        const float* __restrict__ b2,
                        const float* __restrict__ W3,
                        const float* __restrict__ b3,
                        float* __restrict__ out,
                        int out_size)
{
    extern __shared__ float sm[];
    float* sAct  = sm + F_ACT;
    float* sW1   = sm + F_W1;
    float* sWul  = sm + F_WUL;
    float* sW2   = sm + F_W2;
    float* sHead = sm + F_HEAD;
    float* sWV   = sm + F_WV;
    float* sBUL  = sm + F_BUL;
    float* sB1   = sm + F_B1;
    float* sB2   = sm + F_B2;
    float* sW3   = sm + F_W3;

    const int t    = threadIdx.x;
    const int l    = t & 31;
    const int wid  = t >> 5;
    const int g    = wid >> 2;        // warp-group 0/1, owns rows g*64..g*64+63
    const int gw   = wid & 3;         // warp index in group = N quarter
    const int lt   = t & 127;         // thread in group
    const int mtx  = l >> 3, p = l & 7;
    const int base = blockIdx.x * 128;
    const int rowbase = g * 64;

    const uint32_t uAct = smem_u32(sAct);
    const uint32_t uW1  = smem_u32(sW1);
    const uint32_t uWul = smem_u32(sWul);
    const uint32_t uW2  = smem_u32(sW2);

    // per-thread ldmatrix offsets (bytes)
    const uint32_t aoffT   = 4u * (((mtx & 1) * 8 + p) * SST + (mtx >> 1) * 4);
    const uint32_t boffT8  = 4u * (((mtx >> 1) * 8  << 6) + ((mtx & 1) << 5) + (p << 2));
    const uint32_t boffT16 = 4u * (((mtx >> 1) * 16 << 6) + ((mtx & 1) << 5) + (p << 2));

    // ================== gathers (balanced halves) ==================
    {
        const int s = lt;
        const int iid = item_id[base + s];
        if (t < 128) {   // user (tf32-rounded) + head[0..31]
            const int uid = user_id[base + s];
            const float4* up = (const float4*)(user_emb + (size_t)uid * 64);
            const float4* hp = (const float4*)(entity_emb + (size_t)iid * 64);
            #pragma unroll
            for (int j = 0; j < 16; j++) {
                float4 v = up[j];
                *(float4*)&sAct[s * SST + j * 4] =
                    make_float4(tf32r(v.x), tf32r(v.y), tf32r(v.z), tf32r(v.w));
            }
            #pragma unroll
            for (int j = 0; j < 8; j++)
                *(float4*)&sHead[s * HST + j * 4] = hp[j];
        } else {          // item (raw fp32 -> sAct cols 64..127) + head[32..63]
            const float4* ip = (const float4*)(item_emb + (size_t)iid * 64);
            const float4* hp = (const float4*)(entity_emb + (size_t)iid * 64);
            #pragma unroll
            for (int j = 0; j < 16; j++)
                *(float4*)&sAct[s * SST + 64 + j * 4] = ip[j];
            #pragma unroll
            for (int j = 8; j < 16; j++)
                *(float4*)&sHead[s * HST + j * 4] = hp[j];
        }
    }
    // ================== weight staging (blocked, tf32) ==================
    {   // W1: [k=128][n=128] -> blocked K8=16
        const int n = t & 127, k0 = (t >> 7) * 64;
        #pragma unroll 8
        for (int kk = 0; kk < 64; kk++)
            sW1[bwoff(n, k0 + kk, 16)] = tf32r(W1[(k0 + kk) * 128 + n]);
    }
    {   // W2: [k=128][n=64] -> blocked K8=16
        const int n = t & 63, k0 = (t >> 6) * 32;
        #pragma unroll 8
        for (int kk = 0; kk < 32; kk++)
            sW2[bwoff(n, k0 + kk, 16)] = tf32r(W2[(k0 + kk) * 64 + n]);
    }
    {   // Wul: [k=64][n=64] -> blocked K8=8
        const int n = t & 63, k0 = (t >> 6) * 16;
        #pragma unroll
        for (int kk = 0; kk < 16; kk++)
            sWul[bwoff(n, k0 + kk, 8)] = tf32r(Wul[(k0 + kk) * 64 + n]);
    }
    if (t < 64) {
        sWV[t]       = w_vv[t];
        sWV[64 + t]  = w_ev[t];
        sWV[128 + t] = w_ve[t];
        sWV[192 + t] = w_ee[t];
        sBUL[t] = bul[t];
        sB2[t]  = b2[t];
        sW3[t]  = W3[t];
    }
    if (t < 128) sB1[t] = b1[t];
    __syncthreads();   // last block-wide sync; groups are independent below

    const float bvv = b_v[0], bee = b_e[0];

    // ================== 2x (user MLP mma + cross&compress), per group ==================
    #pragma unroll 1
    for (int layer = 0; layer < 2; layer++) {
        // user MLP: M=64 (group rows), N=64, K=64; warp = 4 m-tiles x 2 n-tiles
        float acc[4][2][4];
        #pragma unroll
        for (int mt = 0; mt < 4; mt++)
            #pragma unroll
            for (int nt = 0; nt < 2; nt++)
                #pragma unroll
                for (int i = 0; i < 4; i++) acc[mt][nt][i] = 0.f;
        {
            const int nb0 = gw * 2;
            #pragma unroll
            for (int k8 = 0; k8 < 8; k8++) {
                uint32_t a[4][4], b[4];
                #pragma unroll
                for (int mt = 0; mt < 4; mt++)
                    ldsm4(a[mt], uAct + 4u * ((rowbase + mt * 16) * SST + k8 * 8) + aoffT);
                ldsm4(b, uWul + 4u * ((nb0 * 8 + k8) << 6) + boffT8);
                #pragma unroll
                for (int mt = 0; mt < 4; mt++) {
                    mma8(acc[mt][0], a[mt], b);
                    mma8(acc[mt][1], a[mt], b + 2);
                }
            }
        }
        GBAR();   // group reads of sAct cols 0-63 done
        // epilogue: relu(+bul), tf32, back to sAct cols 0-63 (group rows)
        {
            const int r0b = rowbase + (l >> 2);
            const int cb  = gw * 16 + 2 * (l & 3);
            #pragma unroll
            for (int mt = 0; mt < 4; mt++)
                #pragma unroll
                for (int nt = 0; nt < 2; nt++) {
                    int c = cb + nt * 8;
                    float bb0 = sBUL[c], bb1 = sBUL[c + 1];
                    int r0 = r0b + mt * 16;
                    float2 v0, v1;
                    v0.x = tf32r(fmaxf(acc[mt][nt][0] + bb0, 0.f));
                    v0.y = tf32r(fmaxf(acc[mt][nt][1] + bb1, 0.f));
                    v1.x = tf32r(fmaxf(acc[mt][nt][2] + bb0, 0.f));
                    v1.y = tf32r(fmaxf(acc[mt][nt][3] + bb1, 0.f));
                    *(float2*)&sAct[r0 * SST + c] = v0;
                    *(float2*)&sAct[(r0 + 8) * SST + c] = v1;
                }
        }
        // cross&compress: thread-per-sample on group rows (cols 64-127 + head)
        if (lt < 64) {
            const int s = rowbase + lt;
            float* itp = &sAct[s * SST + 64];
            float* hdp = &sHead[s * HST];
            float s1 = 0.f, s2 = 0.f, s3 = 0.f, s4 = 0.f;
            #pragma unroll
            for (int j = 0; j < 16; j++) {
                float4 iv = *(const float4*)&itp[j * 4];
                float4 hv = *(const float4*)&hdp[j * 4];
                float4 wvv = *(const float4*)&sWV[j * 4];
                float4 wev = *(const float4*)&sWV[64 + j * 4];
                s1 = fmaf(hv.x, wvv.x, fmaf(hv.y, wvv.y, fmaf(hv.z, wvv.z, fmaf(hv.w, wvv.w, s1))));
                s2 = fmaf(iv.x, wev.x, fmaf(iv.y, wev.y, fmaf(iv.z, wev.z, fmaf(iv.w, wev.w, s2))));
                if (layer == 0) {
                    float4 wve = *(const float4*)&sWV[128 + j * 4];
                    float4 wee = *(const float4*)&sWV[192 + j * 4];
                    s3 = fmaf(hv.x, wve.x, fmaf(hv.y, wve.y, fmaf(hv.z, wve.z, fmaf(hv.w, wve.w, s3))));
                    s4 = fmaf(iv.x, wee.x, fmaf(iv.y, wee.y, fmaf(iv.z, wee.z, fmaf(iv.w, wee.w, s4))));
                }
            }
            #pragma unroll
            for (int j = 0; j < 16; j++) {
                float4 iv = *(const float4*)&itp[j * 4];
                float4 hv = *(const float4*)&hdp[j * 4];
                float4 ni;
                ni.x = fmaf(iv.x, s1, fmaf(hv.x, s2, bvv));
                ni.y = fmaf(iv.y, s1, fmaf(hv.y, s2, bvv));
                ni.z = fmaf(iv.z, s1, fmaf(hv.z, s2, bvv));
                ni.w = fmaf(iv.w, s1, fmaf(hv.w, s2, bvv));
                if (layer == 1) {   // last layer: round for GEMM1; head update is dead
                    ni = make_float4(tf32r(ni.x), tf32r(ni.y), tf32r(ni.z), tf32r(ni.w));
                } else {
                    float4 nh;
                    nh.x = fmaf(iv.x, s3, fmaf(hv.x, s4, bee));
                    nh.y = fmaf(iv.y, s3, fmaf(hv.y, s4, bee));
                    nh.z = fmaf(iv.z, s3, fmaf(hv.z, s4, bee));
                    nh.w = fmaf(iv.w, s3, fmaf(hv.w, s4, bee));
                    *(float4*)&hdp[j * 4] = nh;
                }
                *(float4*)&itp[j * 4] = ni;
            }
        }
        GBAR();
    }

    // ================== GEMM1: M=64, N=128, K=128; warp = 4 m-tiles x 4 n-tiles ==================
    {
        float acc[4][4][4];
        #pragma unroll
        for (int mt = 0; mt < 4; mt++)
            #pragma unroll
            for (int nt = 0; nt < 4; nt++)
                #pragma unroll
                for (int i = 0; i < 4; i++) acc[mt][nt][i] = 0.f;
        const int nb0 = gw * 4;
        #pragma unroll
        for (int k8 = 0; k8 < 16; k8++) {
            uint32_t a[4][4], b[8];
            #pragma unroll
            for (int mt = 0; mt < 4; mt++)
                ldsm4(a[mt], uAct + 4u * ((rowbase + mt * 16) * SST + k8 * 8) + aoffT);
            ldsm4(b,     uW1 + 4u * (((nb0 + 0) * 16 + k8) << 6) + boffT16);
            ldsm4(b + 4, uW1 + 4u * (((nb0 + 2) * 16 + k8) << 6) + boffT16);
            #pragma unroll
            for (int mt = 0; mt < 4; mt++) {
                mma8(acc[mt][0], a[mt], b);
                mma8(acc[mt][1], a[mt], b + 2);
                mma8(acc[mt][2], a[mt], b + 4);
                mma8(acc[mt][3], a[mt], b + 6);
            }
        }
        GBAR();
        // epilogue: h1 = relu(+b1), tf32, into sAct cols 0-127 (group rows)
        const int r0b = rowbase + (l >> 2);
        const int cb  = gw * 32 + 2 * (l & 3);
        #pragma unroll
        for (int mt = 0; mt < 4; mt++)
            #pragma unroll
            for (int nt = 0; nt < 4; nt++) {
                int c = cb + nt * 8;
                float bb0 = sB1[c], bb1 = sB1[c + 1];
                int r0 = r0b + mt * 16;
                float2 v0, v1;
                v0.x = tf32r(fmaxf(acc[mt][nt][0] + bb0, 0.f));
                v0.y = tf32r(fmaxf(acc[mt][nt][1] + bb1, 0.f));
                v1.x = tf32r(fmaxf(acc[mt][nt][2] + bb0, 0.f));
                v1.y = tf32r(fmaxf(acc[mt][nt][3] + bb1, 0.f));
                *(float2*)&sAct[r0 * SST + c] = v0;
                *(float2*)&sAct[(r0 + 8) * SST + c] = v1;
            }
        GBAR();
    }

    // ================== GEMM2: M=64, N=64, K=128; warp = 4 m-tiles x 2 n-tiles ==================
    {
        float acc[4][2][4];
        #pragma unroll
        for (int mt = 0; mt < 4; mt++)
            #pragma unroll
            for (int nt = 0; nt < 2; nt++)
                #pragma unroll
                for (int i = 0; i < 4; i++) acc[mt][nt][i] = 0.f;
        const int nb0 = gw * 2;
        #pragma unroll
        for (int k8 = 0; k8 < 16; k8++) {
            uint32_t a[4][4], b[4];
            #pragma unroll
            for (int mt = 0; mt < 4; mt++)
                ldsm4(a[mt], uAct + 4u * ((rowbase + mt * 16) * SST + k8 * 8) + aoffT);
            ldsm4(b, uW2 + 4u * ((nb0 * 16 + k8) << 6) + boffT16);
            #pragma unroll
            for (int mt = 0; mt < 4; mt++) {
                mma8(acc[mt][0], a[mt], b);
                mma8(acc[mt][1], a[mt], b + 2);
            }
        }
        GBAR();
        // epilogue: h2 = relu(+b2) (fp32) into sAct cols 0-63
        const int r0b = rowbase + (l >> 2);
        const int cb  = gw * 16 + 2 * (l & 3);
        #pragma unroll
        for (int mt = 0; mt < 4; mt++)
            #pragma unroll
            for (int nt = 0; nt < 2; nt++) {
                int c = cb + nt * 8;
                float bb0 = sB2[c], bb1 = sB2[c + 1];
                int r0 = r0b + mt * 16;
                float2 v0, v1;
                v0.x = fmaxf(acc[mt][nt][0] + bb0, 0.f);
                v0.y = fmaxf(acc[mt][nt][1] + bb1, 0.f);
                v1.x = fmaxf(acc[mt][nt][2] + bb0, 0.f);
                v1.y = fmaxf(acc[mt][nt][3] + bb1, 0.f);
                *(float2*)&sAct[r0 * SST + c] = v0;
                *(float2*)&sAct[(r0 + 8) * SST + c] = v1;
            }
        GBAR();
    }

    // ================== final 64->1 + relu; rec_target passthrough ==================
    if (lt < 64) {
        const int s = rowbase + lt;
        float psum = 0.f;
        #pragma unroll
        for (int j = 0; j < 16; j++) {
            float4 v = *(const float4*)&sAct[s * SST + j * 4];
            float4 w = *(const float4*)&sW3[j * 4];
            psum = fmaf(v.x, w.x, fmaf(v.y, w.y, fmaf(v.z, w.z, fmaf(v.w, w.w, psum))));
        }
        out[base + s] = fmaxf(psum + b3[0], 0.f);
    } else if (out_size >= 2 * BTOT) {
        const int s = rowbase + (lt - 64);
        out[BTOT + base + s] = rec_target[base + s];
    }
}

extern "C" void kernel_launch(void* const* d_in, const int* in_sizes, int n_in,
                              void* d_out, int out_size)
{
    const int*   user_id    = (const int*)d_in[0];
    const int*   item_id    = (const int*)d_in[1];
    const float* rec_target = (const float*)d_in[2];
    const float* user_emb   = (const float*)d_in[3];
    const float* item_emb   = (const float*)d_in[4];
    const float* entity_emb = (const float*)d_in[5];
    const float* w_vv = (const float*)d_in[6];
    const float* w_ev = (const float*)d_in[7];
    const float* w_ve = (const float*)d_in[8];
    const float* w_ee = (const float*)d_in[9];
    const float* b_v  = (const float*)d_in[10];
    const float* b_e  = (const float*)d_in[11];
    const float* Wul  = (const float*)d_in[12];
    const float* bul  = (const float*)d_in[13];
    const float* W1   = (const float*)d_in[14];
    const float* b1   = (const float*)d_in[15];
    const float* W2   = (const float*)d_in[16];
    const float* b2   = (const float*)d_in[17];
    const float* W3   = (const float*)d_in[18];
    const float* b3   = (const float*)d_in[19];

    cudaFuncSetAttribute(multikr_mma_kernel,
                         cudaFuncAttributeMaxDynamicSharedMemorySize, SMEM_BYTES);

    const int n = in_sizes[0];      // 16384
    const int nblk = n / 128;       // 128 blocks, one wave
    multikr_mma_kernel<<<nblk, NT, SMEM_BYTES>>>(
        user_id, item_id, rec_target, user_emb, item_emb, entity_emb,
        w_vv, w_ev, w_ve, w_ee, b_v, b_e, Wul, bul,
        W1, b1, W2, b2, W3, b3,
        (float*)d_out, out_size);
}

// round 5
// speedup vs baseline: 2.2064x; 1.2318x over previous
#include <cuda_runtime.h>
#include <cstdint>

#define NT 256
#define SST 132            // sAct row stride (floats)
#define HST 68             // sHead row stride
#define BTOT 16384

// ---- dynamic smem layout (float offsets) ----
#define F_ACT   0                        // sAct[128][SST]  = 16896
#define F_W1    (F_ACT + 128*SST)        // 16384 (blocked K8=16)
#define F_WUL   (F_W1 + 16384)           // 4096  (blocked K8=8)
#define F_W2    (F_WUL + 4096)           // 8192  (blocked K8=16)
#define F_HEAD  (F_W2 + 8192)            // sHead[128][HST] = 8704
#define F_WV    (F_HEAD + 128*HST)       // 256: w_vv|w_ev|w_ve|w_ee
#define F_BUL   (F_WV + 256)             // 64
#define F_B1    (F_BUL + 64)             // 128
#define F_B2    (F_B1 + 128)             // 64
#define F_W3    (F_B2 + 64)              // 64
#define SMEM_FLOATS (F_W3 + 64)
#define SMEM_BYTES  (SMEM_FLOATS * 4 + 128)

__device__ __forceinline__ uint32_t smem_u32(const void* p) {
    uint32_t a;
    asm("{ .reg .u64 t; cvta.to.shared.u64 t, %1; cvt.u32.u64 %0, t; }" : "=r"(a) : "l"(p));
    return a;
}
__device__ __forceinline__ void ldsm4(uint32_t* r, uint32_t addr) {
    asm volatile("ldmatrix.sync.aligned.m8n8.x4.shared.b16 {%0,%1,%2,%3}, [%4];"
                 : "=r"(r[0]), "=r"(r[1]), "=r"(r[2]), "=r"(r[3]) : "r"(addr));
}
__device__ __forceinline__ void mma8(float* c, const uint32_t* a, const uint32_t* b) {
    asm("mma.sync.aligned.m16n8k8.row.col.f32.tf32.tf32.f32 "
        "{%0,%1,%2,%3},{%4,%5,%6,%7},{%8,%9},{%0,%1,%2,%3};"
        : "+f"(c[0]), "+f"(c[1]), "+f"(c[2]), "+f"(c[3])
        : "r"(a[0]), "r"(a[1]), "r"(a[2]), "r"(a[3]), "r"(b[0]), "r"(b[1]));
}
// blocked B layout: float index of element (n,k); K8 = K/8
__device__ __forceinline__ int bwoff(int n, int k, int K8) {
    return (((n >> 3) * K8 + (k >> 3)) << 6) + (((k >> 2) & 1) << 5) + ((n & 7) << 2) + (k & 3);
}
__device__ __forceinline__ void cpa16(uint32_t dst, const void* src) {
    asm volatile("cp.async.cg.shared.global [%0], [%1], 16;" :: "r"(dst), "l"(src));
}
__device__ __forceinline__ void cpa4(uint32_t dst, const void* src) {
    asm volatile("cp.async.ca.shared.global [%0], [%1], 4;" :: "r"(dst), "l"(src));
}
#define CP_COMMIT() asm volatile("cp.async.commit_group;" ::: "memory")
#define CP_WAIT(n)  asm volatile("cp.async.wait_group %0;" :: "n"(n) : "memory")
#define GBAR() asm volatile("bar.sync %0, 128;" :: "r"(g + 1) : "memory")

__global__ __launch_bounds__(NT, 1)
void multikr_mma_kernel(const int* __restrict__ user_id,
                        const int* __restrict__ item_id,
                        const float* __restrict__ rec_target,
                        const float* __restrict__ user_emb,
                        const float* __restrict__ item_emb,
                        const float* __restrict__ entity_emb,
                        const float* __restrict__ w_vv,
                        const float* __restrict__ w_ev,
                        const float* __restrict__ w_ve,
                        const float* __restrict__ w_ee,
                        const float* __restrict__ b_v,
                        const float* __restrict__ b_e,
                        const float* __restrict__ Wul,
                        const float* __restrict__ bul,
                        const float* __restrict__ W1,
                        const float* __restrict__ b1,
                        const float* __restrict__ W2,
                        const float* __restrict__ b2,
                        const float* __restrict__ W3,
                        const float* __restrict__ b3,
                        float* __restrict__ out,
                        int out_size)
{
    extern __shared__ float sm[];
    float* sAct  = sm + F_ACT;
    float* sHead = sm + F_HEAD;
    float* sWV   = sm + F_WV;
    float* sBUL  = sm + F_BUL;
    float* sB1   = sm + F_B1;
    float* sB2   = sm + F_B2;
    float* sW3   = sm + F_W3;

    const int t    = threadIdx.x;
    const int l    = t & 31;
    const int wid  = t >> 5;
    const int g    = wid >> 2;        // warp-group 0/1, owns rows g*64..g*64+63
    const int gw   = wid & 3;         // warp index in group = N quarter
    const int lt   = t & 127;         // thread in group
    const int mtx  = l >> 3, p = l & 7;
    const int base = blockIdx.x * 128;
    const int rowbase = g * 64;
    const int gbase = base + rowbase;

    const uint32_t uAct  = smem_u32(sAct);
    const uint32_t uW1s  = smem_u32(sm + F_W1);
    const uint32_t uWuls = smem_u32(sm + F_WUL);
    const uint32_t uW2s  = smem_u32(sm + F_W2);
    const uint32_t uHead = smem_u32(sHead);
    const uint32_t uWVs  = smem_u32(sWV);
    const uint32_t uBULs = smem_u32(sBUL);
    const uint32_t uB1s  = smem_u32(sB1);
    const uint32_t uB2s  = smem_u32(sB2);
    const uint32_t uW3s  = smem_u32(sW3);

    // per-thread ldmatrix offsets (bytes)
    const uint32_t aoffT   = 4u * (((mtx & 1) * 8 + p) * SST + (mtx >> 1) * 4);
    const uint32_t boffT8  = 4u * (((mtx >> 1) * 8  << 6) + ((mtx & 1) << 5) + (p << 2));
    const uint32_t boffT16 = 4u * (((mtx >> 1) * 16 << 6) + ((mtx & 1) << 5) + (p << 2));

    // ============ async front-end: 4 cp.async commit groups ============
    // G0: Wul + user gather (group-local rows) + small params
    #pragma unroll
    for (int i = 0; i < 16; i++) {
        int idx = t + i * 256;
        int n = idx & 63, k = idx >> 6;
        cpa4(uWuls + 4u * bwoff(n, k, 8), Wul + k * 64 + n);
    }
    #pragma unroll
    for (int i = 0; i < 8; i++) {
        int cid = lt + i * 128;
        int s = cid >> 4, j = cid & 15;
        int uid = __ldg(user_id + gbase + s);
        cpa16(uAct + 4u * ((rowbase + s) * SST + j * 4),
              user_emb + (size_t)uid * 64 + j * 4);
    }
    if (t < 64) {
        cpa4(uWVs + 4u * t,          w_vv + t);
        cpa4(uWVs + 4u * (64 + t),   w_ev + t);
        cpa4(uWVs + 4u * (128 + t),  w_ve + t);
        cpa4(uWVs + 4u * (192 + t),  w_ee + t);
        cpa4(uBULs + 4u * t, bul + t);
        cpa4(uB2s + 4u * t,  b2 + t);
        cpa4(uW3s + 4u * t,  W3 + t);
    }
    if (t < 128) cpa4(uB1s + 4u * t, b1 + t);
    CP_COMMIT();
    // G1: item + head gathers (group-local rows)
    #pragma unroll
    for (int i = 0; i < 8; i++) {
        int cid = lt + i * 128;
        int s = cid >> 4, j = cid & 15;
        int iid = __ldg(item_id + gbase + s);
        cpa16(uAct + 4u * ((rowbase + s) * SST + 64 + j * 4),
              item_emb + (size_t)iid * 64 + j * 4);
        cpa16(uHead + 4u * ((rowbase + s) * HST + j * 4),
              entity_emb + (size_t)iid * 64 + j * 4);
    }
    CP_COMMIT();
    // G2: W1 -> blocked
    #pragma unroll 8
    for (int i = 0; i < 64; i++) {
        int idx = t + i * 256;
        int n = idx & 127, k = idx >> 7;
        cpa4(uW1s + 4u * bwoff(n, k, 16), W1 + k * 128 + n);
    }
    CP_COMMIT();
    // G3: W2 -> blocked
    #pragma unroll 8
    for (int i = 0; i < 32; i++) {
        int idx = t + i * 256;
        int n = idx & 63, k = idx >> 6;
        cpa4(uW2s + 4u * bwoff(n, k, 16), W2 + k * 64 + n);
    }
    CP_COMMIT();

    const float bvv = b_v[0], bee = b_e[0];

    CP_WAIT(3);            // Wul + user + smalls landed
    __syncthreads();

    // ============ 2x (user MLP mma + cross&compress), per group ============
    #pragma unroll 1
    for (int layer = 0; layer < 2; layer++) {
        // user MLP: M=64 (group rows), N=64, K=64; warp = 4 m-tiles x 2 n-tiles
        float acc[4][2][4];
        #pragma unroll
        for (int mt = 0; mt < 4; mt++)
            #pragma unroll
            for (int nt = 0; nt < 2; nt++)
                #pragma unroll
                for (int i = 0; i < 4; i++) acc[mt][nt][i] = 0.f;
        {
            const int nb0 = gw * 2;
            #pragma unroll
            for (int k8 = 0; k8 < 8; k8++) {
                uint32_t a[4][4], b[4];
                #pragma unroll
                for (int mt = 0; mt < 4; mt++)
                    ldsm4(a[mt], uAct + 4u * ((rowbase + mt * 16) * SST + k8 * 8) + aoffT);
                ldsm4(b, uWuls + 4u * ((nb0 * 8 + k8) << 6) + boffT8);
                #pragma unroll
                for (int mt = 0; mt < 4; mt++) {
                    mma8(acc[mt][0], a[mt], b);
                    mma8(acc[mt][1], a[mt], b + 2);
                }
            }
        }
        if (layer == 0) CP_WAIT(2);   // item + head landed (own group's cp.asyncs)
        GBAR();                        // + publishes them group-wide; reads of cols 0-63 done
        // epilogue: relu(+bul) back to sAct cols 0-63 (group rows)
        {
            const int r0b = rowbase + (l >> 2);
            const int cb  = gw * 16 + 2 * (l & 3);
            #pragma unroll
            for (int mt = 0; mt < 4; mt++)
                #pragma unroll
                for (int nt = 0; nt < 2; nt++) {
                    int c = cb + nt * 8;
                    float bb0 = sBUL[c], bb1 = sBUL[c + 1];
                    int r0 = r0b + mt * 16;
                    float2 v0, v1;
                    v0.x = fmaxf(acc[mt][nt][0] + bb0, 0.f);
                    v0.y = fmaxf(acc[mt][nt][1] + bb1, 0.f);
                    v1.x = fmaxf(acc[mt][nt][2] + bb0, 0.f);
                    v1.y = fmaxf(acc[mt][nt][3] + bb1, 0.f);
                    *(float2*)&sAct[r0 * SST + c] = v0;
                    *(float2*)&sAct[(r0 + 8) * SST + c] = v1;
                }
        }
        // cross&compress: 2 threads per sample (shfl-pair reduce)
        {
            const int s  = rowbase + (lt >> 1);
            const int kh = lt & 1;
            float* itp = &sAct[s * SST + 64 + kh * 32];
            float* hdp = &sHead[s * HST + kh * 32];
            const float* wv0 = &sWV[kh * 32];
            float s1 = 0.f, s2 = 0.f, s3 = 0.f, s4 = 0.f;
            #pragma unroll
            for (int j = 0; j < 8; j++) {
                float4 iv = *(const float4*)&itp[j * 4];
                float4 hv = *(const float4*)&hdp[j * 4];
                float4 wvv = *(const float4*)&wv0[j * 4];
                float4 wev = *(const float4*)&wv0[64 + j * 4];
                s1 = fmaf(hv.x, wvv.x, fmaf(hv.y, wvv.y, fmaf(hv.z, wvv.z, fmaf(hv.w, wvv.w, s1))));
                s2 = fmaf(iv.x, wev.x, fmaf(iv.y, wev.y, fmaf(iv.z, wev.z, fmaf(iv.w, wev.w, s2))));
                if (layer == 0) {
                    float4 wve = *(const float4*)&wv0[128 + j * 4];
                    float4 wee = *(const float4*)&wv0[192 + j * 4];
                    s3 = fmaf(hv.x, wve.x, fmaf(hv.y, wve.y, fmaf(hv.z, wve.z, fmaf(hv.w, wve.w, s3))));
                    s4 = fmaf(iv.x, wee.x, fmaf(iv.y, wee.y, fmaf(iv.z, wee.z, fmaf(iv.w, wee.w, s4))));
                }
            }
            s1 += __shfl_xor_sync(0xffffffffu, s1, 1);
            s2 += __shfl_xor_sync(0xffffffffu, s2, 1);
            if (layer == 0) {
                s3 += __shfl_xor_sync(0xffffffffu, s3, 1);
                s4 += __shfl_xor_sync(0xffffffffu, s4, 1);
            }
            #pragma unroll
            for (int j = 0; j < 8; j++) {
                float4 iv = *(const float4*)&itp[j * 4];
                float4 hv = *(const float4*)&hdp[j * 4];
                float4 ni;
                ni.x = fmaf(iv.x, s1, fmaf(hv.x, s2, bvv));
                ni.y = fmaf(iv.y, s1, fmaf(hv.y, s2, bvv));
                ni.z = fmaf(iv.z, s1, fmaf(hv.z, s2, bvv));
                ni.w = fmaf(iv.w, s1, fmaf(hv.w, s2, bvv));
                *(float4*)&itp[j * 4] = ni;
                if (layer == 0) {   // head update dead after last layer
                    float4 nh;
                    nh.x = fmaf(iv.x, s3, fmaf(hv.x, s4, bee));
                    nh.y = fmaf(iv.y, s3, fmaf(hv.y, s4, bee));
                    nh.z = fmaf(iv.z, s3, fmaf(hv.z, s4, bee));
                    nh.w = fmaf(iv.w, s3, fmaf(hv.w, s4, bee));
                    *(float4*)&hdp[j * 4] = nh;
                }
            }
        }
        GBAR();
    }

    // ============ GEMM1: M=64, N=128, K=128; warp = 4 m-tiles x 4 n-tiles ============
    CP_WAIT(1);            // W1 landed (this thread); barrier publishes all threads'
    __syncthreads();
    {
        float acc[4][4][4];
        #pragma unroll
        for (int mt = 0; mt < 4; mt++)
            #pragma unroll
            for (int nt = 0; nt < 4; nt++)
                #pragma unroll
                for (int i = 0; i < 4; i++) acc[mt][nt][i] = 0.f;
        const int nb0 = gw * 4;
        #pragma unroll
        for (int k8 = 0; k8 < 16; k8++) {
            uint32_t a[4][4], b[8];
            #pragma unroll
            for (int mt = 0; mt < 4; mt++)
                ldsm4(a[mt], uAct + 4u * ((rowbase + mt * 16) * SST + k8 * 8) + aoffT);
            ldsm4(b,     uW1s + 4u * (((nb0 + 0) * 16 + k8) << 6) + boffT16);
            ldsm4(b + 4, uW1s + 4u * (((nb0 + 2) * 16 + k8) << 6) + boffT16);
            #pragma unroll
            for (int mt = 0; mt < 4; mt++) {
                mma8(acc[mt][0], a[mt], b);
                mma8(acc[mt][1], a[mt], b + 2);
                mma8(acc[mt][2], a[mt], b + 4);
                mma8(acc[mt][3], a[mt], b + 6);
            }
        }
        GBAR();
        // epilogue: h1 = relu(+b1) into sAct cols 0-127 (group rows)
        const int r0b = rowbase + (l >> 2);
        const int cb  = gw * 32 + 2 * (l & 3);
        #pragma unroll
        for (int mt = 0; mt < 4; mt++)
            #pragma unroll
            for (int nt = 0; nt < 4; nt++) {
                int c = cb + nt * 8;
                float bb0 = sB1[c], bb1 = sB1[c + 1];
                int r0 = r0b + mt * 16;
                float2 v0, v1;
                v0.x = fmaxf(acc[mt][nt][0] + bb0, 0.f);
                v0.y = fmaxf(acc[mt][nt][1] + bb1, 0.f);
                v1.x = fmaxf(acc[mt][nt][2] + bb0, 0.f);
                v1.y = fmaxf(acc[mt][nt][3] + bb1, 0.f);
                *(float2*)&sAct[r0 * SST + c] = v0;
                *(float2*)&sAct[(r0 + 8) * SST + c] = v1;
            }
    }
    CP_WAIT(0);            // W2 landed
    __syncthreads();       // also separates GEMM1 epilogue writes from GEMM2 reads

    // ============ GEMM2: M=64, N=64, K=128; warp = 4 m-tiles x 2 n-tiles ============
    {
        float acc[4][2][4];
        #pragma unroll
        for (int mt = 0; mt < 4; mt++)
            #pragma unroll
            for (int nt = 0; nt < 2; nt++)
                #pragma unroll
                for (int i = 0; i < 4; i++) acc[mt][nt][i] = 0.f;
        const int nb0 = gw * 2;
        #pragma unroll
        for (int k8 = 0; k8 < 16; k8++) {
            uint32_t a[4][4], b[4];
            #pragma unroll
            for (int mt = 0; mt < 4; mt++)
                ldsm4(a[mt], uAct + 4u * ((rowbase + mt * 16) * SST + k8 * 8) + aoffT);
            ldsm4(b, uW2s + 4u * ((nb0 * 16 + k8) << 6) + boffT16);
            #pragma unroll
            for (int mt = 0; mt < 4; mt++) {
                mma8(acc[mt][0], a[mt], b);
                mma8(acc[mt][1], a[mt], b + 2);
            }
        }
        GBAR();
        // epilogue: h2 = relu(+b2) into sAct cols 0-63
        const int r0b = rowbase + (l >> 2);
        const int cb  = gw * 16 + 2 * (l & 3);
        #pragma unroll
        for (int mt = 0; mt < 4; mt++)
            #pragma unroll
            for (int nt = 0; nt < 2; nt++) {
                int c = cb + nt * 8;
                float bb0 = sB2[c], bb1 = sB2[c + 1];
                int r0 = r0b + mt * 16;
                float2 v0, v1;
                v0.x = fmaxf(acc[mt][nt][0] + bb0, 0.f);
                v0.y = fmaxf(acc[mt][nt][1] + bb1, 0.f);
                v1.x = fmaxf(acc[mt][nt][2] + bb0, 0.f);
                v1.y = fmaxf(acc[mt][nt][3] + bb1, 0.f);
                *(float2*)&sAct[r0 * SST + c] = v0;
                *(float2*)&sAct[(r0 + 8) * SST + c] = v1;
            }
        GBAR();
    }

    // ============ final 64->1 + relu; rec_target passthrough ============
    if (lt < 64) {
        const int s = rowbase + lt;
        float psum = 0.f;
        #pragma unroll
        for (int j = 0; j < 16; j++) {
            float4 v = *(const float4*)&sAct[s * SST + j * 4];
            float4 w = *(const float4*)&sW3[j * 4];
            psum = fmaf(v.x, w.x, fmaf(v.y, w.y, fmaf(v.z, w.z, fmaf(v.w, w.w, psum))));
        }
        out[base + s] = fmaxf(psum + b3[0], 0.f);
    } else if (out_size >= 2 * BTOT) {
        const int s = rowbase + (lt - 64);
        out[BTOT + base + s] = rec_target[base + s];
    }
}

extern "C" void kernel_launch(void* const* d_in, const int* in_sizes, int n_in,
                              void* d_out, int out_size)
{
    const int*   user_id    = (const int*)d_in[0];
    const int*   item_id    = (const int*)d_in[1];
    const float* rec_target = (const float*)d_in[2];
    const float* user_emb   = (const float*)d_in[3];
    const float* item_emb   = (const float*)d_in[4];
    const float* entity_emb = (const float*)d_in[5];
    const float* w_vv = (const float*)d_in[6];
    const float* w_ev = (const float*)d_in[7];
    const float* w_ve = (const float*)d_in[8];
    const float* w_ee = (const float*)d_in[9];
    const float* b_v  = (const float*)d_in[10];
    const float* b_e  = (const float*)d_in[11];
    const float* Wul  = (const float*)d_in[12];
    const float* bul  = (const float*)d_in[13];
    const float* W1   = (const float*)d_in[14];
    const float* b1   = (const float*)d_in[15];
    const float* W2   = (const float*)d_in[16];
    const float* b2   = (const float*)d_in[17];
    const float* W3   = (const float*)d_in[18];
    const float* b3   = (const float*)d_in[19];

    cudaFuncSetAttribute(multikr_mma_kernel,
                         cudaFuncAttributeMaxDynamicSharedMemorySize, SMEM_BYTES);

    const int n = in_sizes[0];      // 16384
    const int nblk = n / 128;       // 128 blocks, one wave
    multikr_mma_kernel<<<nblk, NT, SMEM_BYTES>>>(
        user_id, item_id, rec_target, user_emb, item_emb, entity_emb,
        w_vv, w_ev, w_ve, w_ee, b_v, b_e, Wul, bul,
        W1, b1, W2, b2, W3, b3,
        (float*)d_out, out_size);
}

// round 6
// speedup vs baseline: 2.4744x; 1.1214x over previous
#include <cuda_runtime.h>
#include <cstdint>

#define NT 256
#define SST 132            // sAct row stride (floats)
#define HST 68             // sHead row stride
#define BTOT 16384

// ---- dynamic smem layout (float offsets) ----
#define F_ACT   0                        // sAct[128][SST]
#define F_W1    (F_ACT + 128*SST)        // 16384 (blocked K8=16)
#define F_WUL   (F_W1 + 16384)           // 4096  (blocked K8=8)
#define F_W2    (F_WUL + 4096)           // 8192  (blocked K8=16)
#define F_HEAD  (F_W2 + 8192)            // sHead[128][HST]
#define F_WV    (F_HEAD + 128*HST)       // 256: w_vv|w_ev|w_ve|w_ee
#define F_BUL   (F_WV + 256)             // 64
#define F_B1    (F_BUL + 64)             // 128
#define F_B2    (F_B1 + 128)             // 64
#define F_W3    (F_B2 + 64)              // 64
#define F_OUT   (F_W3 + 64)              // 128 (output accumulator)
#define SMEM_FLOATS (F_OUT + 128)
#define SMEM_BYTES  (SMEM_FLOATS * 4 + 128)

__device__ __forceinline__ uint32_t smem_u32(const void* p) {
    uint32_t a;
    asm("{ .reg .u64 t; cvta.to.shared.u64 t, %1; cvt.u32.u64 %0, t; }" : "=r"(a) : "l"(p));
    return a;
}
__device__ __forceinline__ void ldsm4(uint32_t* r, uint32_t addr) {
    asm volatile("ldmatrix.sync.aligned.m8n8.x4.shared.b16 {%0,%1,%2,%3}, [%4];"
                 : "=r"(r[0]), "=r"(r[1]), "=r"(r[2]), "=r"(r[3]) : "r"(addr));
}
__device__ __forceinline__ void mma8(float* c, const uint32_t* a, const uint32_t* b) {
    asm("mma.sync.aligned.m16n8k8.row.col.f32.tf32.tf32.f32 "
        "{%0,%1,%2,%3},{%4,%5,%6,%7},{%8,%9},{%0,%1,%2,%3};"
        : "+f"(c[0]), "+f"(c[1]), "+f"(c[2]), "+f"(c[3])
        : "r"(a[0]), "r"(a[1]), "r"(a[2]), "r"(a[3]), "r"(b[0]), "r"(b[1]));
}
// blocked B layout: float index of element (n,k); K8 = K/8
__device__ __forceinline__ int bwoff(int n, int k, int K8) {
    return (((n >> 3) * K8 + (k >> 3)) << 6) + (((k >> 2) & 1) << 5) + ((n & 7) << 2) + (k & 3);
}
__device__ __forceinline__ void cpa16(uint32_t dst, const void* src) {
    asm volatile("cp.async.cg.shared.global [%0], [%1], 16;" :: "r"(dst), "l"(src));
}
__device__ __forceinline__ void cpa4(uint32_t dst, const void* src) {
    asm volatile("cp.async.ca.shared.global [%0], [%1], 4;" :: "r"(dst), "l"(src));
}
#define CP_COMMIT() asm volatile("cp.async.commit_group;" ::: "memory")
#define CP_WAIT(n)  asm volatile("cp.async.wait_group %0;" :: "n"(n) : "memory")
#define BAR_U() asm volatile("bar.sync 1, 128;" ::: "memory")
#define BAR_C() asm volatile("bar.sync 2, 128;" ::: "memory")

__global__ __launch_bounds__(NT, 1)
void multikr_mma_kernel(const int* __restrict__ user_id,
                        const int* __restrict__ item_id,
                        const float* __restrict__ rec_target,
                        const float* __restrict__ user_emb,
                        const float* __restrict__ item_emb,
                        const float* __restrict__ entity_emb,
                        const float* __restrict__ w_vv,
                        const float* __restrict__ w_ev,
                        const float* __restrict__ w_ve,
                        const float* __restrict__ w_ee,
                        const float* __restrict__ b_v,
                        const float* __restrict__ b_e,
                        const float* __restrict__ Wul,
                        const float* __restrict__ bul,
                        const float* __restrict__ W1,
                        const float* __restrict__ b1,
                        const float* __restrict__ W2,
                        const float* __restrict__ b2,
                        const float* __restrict__ W3,
                        const float* __restrict__ b3,
                        float* __restrict__ out,
                        int out_size)
{
    extern __shared__ float sm[];
    float* sAct  = sm + F_ACT;
    float* sHead = sm + F_HEAD;
    float* sWV   = sm + F_WV;
    float* sBUL  = sm + F_BUL;
    float* sB1   = sm + F_B1;
    float* sB2   = sm + F_B2;
    float* sW3   = sm + F_W3;
    float* sOut  = sm + F_OUT;

    const int t    = threadIdx.x;
    const int l    = t & 31;
    const int wid  = t >> 5;
    const int mtx  = l >> 3, p = l & 7;
    const int base = blockIdx.x * 128;

    const uint32_t uAct  = smem_u32(sAct);
    const uint32_t uW1s  = smem_u32(sm + F_W1);
    const uint32_t uWuls = smem_u32(sm + F_WUL);
    const uint32_t uW2s  = smem_u32(sm + F_W2);
    const uint32_t uHead = smem_u32(sHead);
    const uint32_t uWVs  = smem_u32(sWV);
    const uint32_t uBULs = smem_u32(sBUL);
    const uint32_t uB1s  = smem_u32(sB1);
    const uint32_t uB2s  = smem_u32(sB2);
    const uint32_t uW3s  = smem_u32(sW3);

    // per-thread ldmatrix offsets (bytes)
    const uint32_t aoffT   = 4u * (((mtx & 1) * 8 + p) * SST + (mtx >> 1) * 4);
    const uint32_t boffT8  = 4u * (((mtx >> 1) * 8  << 6) + ((mtx & 1) << 5) + (p << 2));
    const uint32_t boffT16 = 4u * (((mtx >> 1) * 16 << 6) + ((mtx & 1) << 5) + (p << 2));

    // ============ async front-end: 4 commit groups (content split by role) ============
    if (t < 128) {
        // G0 (user warps): Wul blocked + user gather + bul
        #pragma unroll
        for (int i = 0; i < 32; i++) {
            int idx = t + i * 128;
            cpa4(uWuls + 4u * bwoff(idx & 63, idx >> 6, 8), Wul + (idx >> 6) * 64 + (idx & 63));
        }
        #pragma unroll
        for (int i = 0; i < 16; i++) {
            int cid = t + i * 128;
            int s = cid >> 4, j = cid & 15;
            int uid = __ldg(user_id + base + s);
            cpa16(uAct + 4u * (s * SST + j * 4), user_emb + (size_t)uid * 64 + j * 4);
        }
        if (t < 64) cpa4(uBULs + 4u * t, bul + t);
        CP_COMMIT();
        CP_COMMIT();    // empty G1
    } else {
        const int ct = t - 128;
        // G0 (cross warps): WV + b1/b2/w3
        {
            const float* w1p = (ct < 64) ? (w_vv + ct) : (w_ev + ct - 64);
            const float* w2p = (ct < 64) ? (w_ve + ct) : (w_ee + ct - 64);
            cpa4(uWVs + 4u * ct, w1p);
            cpa4(uWVs + 4u * (128 + ct), w2p);
            cpa4(uB1s + 4u * ct, b1 + ct);
            if (ct < 64) { cpa4(uB2s + 4u * ct, b2 + ct); cpa4(uW3s + 4u * ct, W3 + ct); }
        }
        CP_COMMIT();
        // G1: item + head gathers
        #pragma unroll
        for (int i = 0; i < 16; i++) {
            int cid = ct + i * 128;
            int s = cid >> 4, j = cid & 15;
            int iid = __ldg(item_id + base + s);
            cpa16(uAct + 4u * (s * SST + 64 + j * 4), item_emb + (size_t)iid * 64 + j * 4);
            cpa16(uHead + 4u * (s * HST + j * 4), entity_emb + (size_t)iid * 64 + j * 4);
        }
        CP_COMMIT();
    }
    // G2: W1 (all threads)
    #pragma unroll 8
    for (int i = 0; i < 64; i++) {
        int idx = t + i * 256;
        cpa4(uW1s + 4u * bwoff(idx & 127, idx >> 7, 16), W1 + (idx >> 7) * 128 + (idx & 127));
    }
    CP_COMMIT();
    // G3: W2 (all threads)
    #pragma unroll 8
    for (int i = 0; i < 32; i++) {
        int idx = t + i * 256;
        cpa4(uW2s + 4u * bwoff(idx & 63, idx >> 6, 16), W2 + (idx >> 6) * 64 + (idx & 63));
    }
    CP_COMMIT();

    // rec_target passthrough (independent; overlaps cp.async)
    if (t < 128 && out_size >= 2 * BTOT)
        out[BTOT + base + t] = __ldg(rec_target + base + t);

    // ============ phase 1: user MLP chain (warps 0-3) || cross chain (warps 4-7) ============
    if (t < 128) {
        const int wm = wid & 1, wn = wid >> 1;     // M half, N half (32 cols)
        CP_WAIT(3);
        BAR_U();                                   // Wul + user + bul visible
        #pragma unroll 1
        for (int layer = 0; layer < 2; layer++) {
            float acc[4][4][4];
            #pragma unroll
            for (int mt = 0; mt < 4; mt++)
                #pragma unroll
                for (int nt = 0; nt < 4; nt++)
                    #pragma unroll
                    for (int i = 0; i < 4; i++) acc[mt][nt][i] = 0.f;
            const int nb0 = wn * 4;
            #pragma unroll
            for (int k8 = 0; k8 < 8; k8++) {
                uint32_t a[4][4], b[8];
                #pragma unroll
                for (int mt = 0; mt < 4; mt++)
                    ldsm4(a[mt], uAct + 4u * ((wm * 64 + mt * 16) * SST + k8 * 8) + aoffT);
                ldsm4(b,     uWuls + 4u * (((nb0 + 0) * 8 + k8) << 6) + boffT8);
                ldsm4(b + 4, uWuls + 4u * (((nb0 + 2) * 8 + k8) << 6) + boffT8);
                #pragma unroll
                for (int mt = 0; mt < 4; mt++) {
                    mma8(acc[mt][0], a[mt], b);
                    mma8(acc[mt][1], a[mt], b + 2);
                    mma8(acc[mt][2], a[mt], b + 4);
                    mma8(acc[mt][3], a[mt], b + 6);
                }
            }
            BAR_U();     // all user-warp reads of cols 0-63 done
            const int r0b = wm * 64 + (l >> 2);
            const int cb  = wn * 32 + 2 * (l & 3);
            #pragma unroll
            for (int mt = 0; mt < 4; mt++)
                #pragma unroll
                for (int nt = 0; nt < 4; nt++) {
                    int c = cb + nt * 8;
                    float bb0 = sBUL[c], bb1 = sBUL[c + 1];
                    int r0 = r0b + mt * 16;
                    float2 v0, v1;
                    v0.x = fmaxf(acc[mt][nt][0] + bb0, 0.f);
                    v0.y = fmaxf(acc[mt][nt][1] + bb1, 0.f);
                    v1.x = fmaxf(acc[mt][nt][2] + bb0, 0.f);
                    v1.y = fmaxf(acc[mt][nt][3] + bb1, 0.f);
                    *(float2*)&sAct[r0 * SST + c] = v0;
                    *(float2*)&sAct[(r0 + 8) * SST + c] = v1;
                }
            BAR_U();     // epilogue writes visible before next layer reads
        }
        sOut[t] = 0.f;   // zero output accumulator (visible after next block sync)
    } else {
        const int s = t - 128;                     // 1 thread per sample
        const float bvv = __ldg(b_v), bee = __ldg(b_e);
        CP_WAIT(2);
        BAR_C();                                   // WV + item + head visible
        float* itp = &sAct[s * SST + 64];
        float* hdp = &sHead[s * HST];
        #pragma unroll 1
        for (int layer = 0; layer < 2; layer++) {
            float s1 = 0.f, s2 = 0.f, s3 = 0.f, s4 = 0.f;
            #pragma unroll
            for (int j = 0; j < 16; j++) {
                float4 iv = *(const float4*)&itp[j * 4];
                float4 hv = *(const float4*)&hdp[j * 4];
                float4 wvv = *(const float4*)&sWV[j * 4];
                float4 wev = *(const float4*)&sWV[64 + j * 4];
                s1 = fmaf(hv.x, wvv.x, fmaf(hv.y, wvv.y, fmaf(hv.z, wvv.z, fmaf(hv.w, wvv.w, s1))));
                s2 = fmaf(iv.x, wev.x, fmaf(iv.y, wev.y, fmaf(iv.z, wev.z, fmaf(iv.w, wev.w, s2))));
                if (layer == 0) {
                    float4 wve = *(const float4*)&sWV[128 + j * 4];
                    float4 wee = *(const float4*)&sWV[192 + j * 4];
                    s3 = fmaf(hv.x, wve.x, fmaf(hv.y, wve.y, fmaf(hv.z, wve.z, fmaf(hv.w, wve.w, s3))));
                    s4 = fmaf(iv.x, wee.x, fmaf(iv.y, wee.y, fmaf(iv.z, wee.z, fmaf(iv.w, wee.w, s4))));
                }
            }
            #pragma unroll
            for (int j = 0; j < 16; j++) {
                float4 iv = *(const float4*)&itp[j * 4];
                float4 hv = *(const float4*)&hdp[j * 4];
                float4 ni;
                ni.x = fmaf(iv.x, s1, fmaf(hv.x, s2, bvv));
                ni.y = fmaf(iv.y, s1, fmaf(hv.y, s2, bvv));
                ni.z = fmaf(iv.z, s1, fmaf(hv.z, s2, bvv));
                ni.w = fmaf(iv.w, s1, fmaf(hv.w, s2, bvv));
                *(float4*)&itp[j * 4] = ni;
                if (layer == 0) {    // head update dead after last layer
                    float4 nh;
                    nh.x = fmaf(iv.x, s3, fmaf(hv.x, s4, bee));
                    nh.y = fmaf(iv.y, s3, fmaf(hv.y, s4, bee));
                    nh.z = fmaf(iv.z, s3, fmaf(hv.z, s4, bee));
                    nh.w = fmaf(iv.w, s3, fmaf(hv.w, s4, bee));
                    *(float4*)&hdp[j * 4] = nh;
                }
            }
        }
    }

    CP_WAIT(1);          // W1 landed
    __syncthreads();     // concat point: user cols + item cols + W1 all visible

    // ============ GEMM1: M=128, N=128, K=128; 8 warps = 2M x 4N ============
    const int wm = wid & 1, wn4 = wid >> 1;
    {
        float acc[4][4][4];
        #pragma unroll
        for (int mt = 0; mt < 4; mt++)
            #pragma unroll
            for (int nt = 0; nt < 4; nt++)
                #pragma unroll
                for (int i = 0; i < 4; i++) acc[mt][nt][i] = 0.f;
        const int nb0 = wn4 * 4;
        #pragma unroll
        for (int k8 = 0; k8 < 16; k8++) {
            uint32_t a[4][4], b[8];
            #pragma unroll
            for (int mt = 0; mt < 4; mt++)
                ldsm4(a[mt], uAct + 4u * ((wm * 64 + mt * 16) * SST + k8 * 8) + aoffT);
            ldsm4(b,     uW1s + 4u * (((nb0 + 0) * 16 + k8) << 6) + boffT16);
            ldsm4(b + 4, uW1s + 4u * (((nb0 + 2) * 16 + k8) << 6) + boffT16);
            #pragma unroll
            for (int mt = 0; mt < 4; mt++) {
                mma8(acc[mt][0], a[mt], b);
                mma8(acc[mt][1], a[mt], b + 2);
                mma8(acc[mt][2], a[mt], b + 4);
                mma8(acc[mt][3], a[mt], b + 6);
            }
        }
        __syncthreads();    // all reads done before h1 overwrites sAct
        const int r0b = wm * 64 + (l >> 2);
        const int cb  = wn4 * 32 + 2 * (l & 3);
        #pragma unroll
        for (int mt = 0; mt < 4; mt++)
            #pragma unroll
            for (int nt = 0; nt < 4; nt++) {
                int c = cb + nt * 8;
                float bb0 = sB1[c], bb1 = sB1[c + 1];
                int r0 = r0b + mt * 16;
                float2 v0, v1;
                v0.x = fmaxf(acc[mt][nt][0] + bb0, 0.f);
                v0.y = fmaxf(acc[mt][nt][1] + bb1, 0.f);
                v1.x = fmaxf(acc[mt][nt][2] + bb0, 0.f);
                v1.y = fmaxf(acc[mt][nt][3] + bb1, 0.f);
                *(float2*)&sAct[r0 * SST + c] = v0;
                *(float2*)&sAct[(r0 + 8) * SST + c] = v1;
            }
    }
    CP_WAIT(0);          // W2 landed
    __syncthreads();     // h1 visible

    // ============ GEMM2 (M=128, N=64; 2M x 4N of 16) + fused final 64->1 ============
    {
        float acc[4][2][4];
        #pragma unroll
        for (int mt = 0; mt < 4; mt++)
            #pragma unroll
            for (int nt = 0; nt < 2; nt++)
                #pragma unroll
                for (int i = 0; i < 4; i++) acc[mt][nt][i] = 0.f;
        const int nb0 = wn4 * 2;
        #pragma unroll
        for (int k8 = 0; k8 < 16; k8++) {
            uint32_t a[4][4], b[4];
            #pragma unroll
            for (int mt = 0; mt < 4; mt++)
                ldsm4(a[mt], uAct + 4u * ((wm * 64 + mt * 16) * SST + k8 * 8) + aoffT);
            ldsm4(b, uW2s + 4u * ((nb0 * 16 + k8) << 6) + boffT16);
            #pragma unroll
            for (int mt = 0; mt < 4; mt++) {
                mma8(acc[mt][0], a[mt], b);
                mma8(acc[mt][1], a[mt], b + 2);
            }
        }
        // fused: p[row] += relu(h2+b2)*w3, reduce over lane column-group, atomic into sOut
        const int cb = wn4 * 16 + 2 * (l & 3);
        float part[4][2];
        #pragma unroll
        for (int mt = 0; mt < 4; mt++) { part[mt][0] = 0.f; part[mt][1] = 0.f; }
        #pragma unroll
        for (int nt = 0; nt < 2; nt++) {
            int c = cb + nt * 8;
            float bb0 = sB2[c], bb1 = sB2[c + 1];
            float w30 = sW3[c], w31 = sW3[c + 1];
            #pragma unroll
            for (int mt = 0; mt < 4; mt++) {
                part[mt][0] = fmaf(fmaxf(acc[mt][nt][0] + bb0, 0.f), w30,
                              fmaf(fmaxf(acc[mt][nt][1] + bb1, 0.f), w31, part[mt][0]));
                part[mt][1] = fmaf(fmaxf(acc[mt][nt][2] + bb0, 0.f), w30,
                              fmaf(fmaxf(acc[mt][nt][3] + bb1, 0.f), w31, part[mt][1]));
            }
        }
        #pragma unroll
        for (int mt = 0; mt < 4; mt++)
            #pragma unroll
            for (int rh = 0; rh < 2; rh++) {
                part[mt][rh] += __shfl_xor_sync(0xffffffffu, part[mt][rh], 1);
                part[mt][rh] += __shfl_xor_sync(0xffffffffu, part[mt][rh], 2);
            }
        if ((l & 3) == 0) {
            const int r0b = wm * 64 + (l >> 2);
            #pragma unroll
            for (int mt = 0; mt < 4; mt++) {
                atomicAdd(&sOut[r0b + mt * 16],     part[mt][0]);
                atomicAdd(&sOut[r0b + mt * 16 + 8], part[mt][1]);
            }
        }
    }
    __syncthreads();

    // ============ output ============
    if (t < 128)
        out[base + t] = fmaxf(sOut[t] + __ldg(b3), 0.f);
}

extern "C" void kernel_launch(void* const* d_in, const int* in_sizes, int n_in,
                              void* d_out, int out_size)
{
    const int*   user_id    = (const int*)d_in[0];
    const int*   item_id    = (const int*)d_in[1];
    const float* rec_target = (const float*)d_in[2];
    const float* user_emb   = (const float*)d_in[3];
    const float* item_emb   = (const float*)d_in[4];
    const float* entity_emb = (const float*)d_in[5];
    const float* w_vv = (const float*)d_in[6];
    const float* w_ev = (const float*)d_in[7];
    const float* w_ve = (const float*)d_in[8];
    const float* w_ee = (const float*)d_in[9];
    const float* b_v  = (const float*)d_in[10];
    const float* b_e  = (const float*)d_in[11];
    const float* Wul  = (const float*)d_in[12];
    const float* bul  = (const float*)d_in[13];
    const float* W1   = (const float*)d_in[14];
    const float* b1   = (const float*)d_in[15];
    const float* W2   = (const float*)d_in[16];
    const float* b2   = (const float*)d_in[17];
    const float* W3   = (const float*)d_in[18];
    const float* b3   = (const float*)d_in[19];

    cudaFuncSetAttribute(multikr_mma_kernel,
                         cudaFuncAttributeMaxDynamicSharedMemorySize, SMEM_BYTES);

    const int n = in_sizes[0];      // 16384
    const int nblk = n / 128;       // 128 blocks, one wave
    multikr_mma_kernel<<<nblk, NT, SMEM_BYTES>>>(
        user_id, item_id, rec_target, user_emb, item_emb, entity_emb,
        w_vv, w_ev, w_ve, w_ee, b_v, b_e, Wul, bul,
        W1, b1, W2, b2, W3, b3,
        (float*)d_out, out_size);
}